// round 12
// baseline (speedup 1.0000x reference)
#include <cuda_runtime.h>
#include <cstdint>

#define DB 64
#define DS 2048
#define DI 64
#define DH 128

typedef unsigned long long u64;

// ---------------- scratch (__device__ globals) -------------------------------
__device__ float g_wx0 [DB * DS * DH];   // x @ w0 (precomputed by gemm)
__device__ float g_out0[DB * DS * DH];   // layer-0 outputs
__device__ float g_wx1 [DB * DS * DH];   // out0 @ w1 (wx1 chase CTAs)
__device__ int   g_prog[DB * 32];        // [b*32]=p0  [+16]=pwx1

// ---------------- packed f32x2 helpers ---------------------------------------
__device__ __forceinline__ u64 ffma2(u64 a, u64 b, u64 c) {
    u64 d; asm("fma.rn.f32x2 %0, %1, %2, %3;" : "=l"(d) : "l"(a), "l"(b), "l"(c)); return d;
}
__device__ __forceinline__ u64 fadd2(u64 a, u64 b) {
    u64 d; asm("add.rn.f32x2 %0, %1, %2;" : "=l"(d) : "l"(a), "l"(b)); return d;
}
__device__ __forceinline__ u64 dup2(float x) {
    u64 d; asm("mov.b64 %0, {%1, %2};" : "=l"(d) : "f"(x), "f"(x)); return d;
}
__device__ __forceinline__ float2 unp2(u64 v) {
    float lo, hi; asm("mov.b64 {%0, %1}, %2;" : "=f"(lo), "=f"(hi) : "l"(v));
    return make_float2(lo, hi);
}

// ---------------- fast gates (validated, rel_err ~1.3e-7) ---------------------
__device__ __forceinline__ float sigm_fast(float x) {
    float t, r;
    asm("ex2.approx.f32 %0, %1;" : "=f"(t) : "f"(-1.4426950408889634f * x));
    asm("rcp.approx.f32 %0, %1;" : "=f"(r) : "f"(1.0f + t));
    return r;
}
__device__ __forceinline__ float tanh_fast(float x) {
    float t, r;
    asm("ex2.approx.f32 %0, %1;" : "=f"(t) : "f"(-2.8853900817779268f * x));
    asm("rcp.approx.f32 %0, %1;" : "=f"(r) : "f"(1.0f + t));
    return __fmaf_rn(2.0f, r, -1.0f);
}

// ---------------- flags --------------------------------------------------------
__device__ __forceinline__ int ld_acq(const int* p) {
    int v; asm volatile("ld.acquire.gpu.b32 %0, [%1];" : "=r"(v) : "l"(p)); return v;
}
__device__ __forceinline__ void st_rel(int* p, int v) {
    asm volatile("st.release.gpu.b32 [%0], %1;" :: "l"(p), "r"(v));
}
__device__ __forceinline__ void spin_ge(const int* p, int target) {
    while (ld_acq(p) < target) __nanosleep(32);
}

// ============================================================================
// GEMM: OUT[row, 0:128] = X[row, 0:K] @ W[K,128]; block 0 also resets flags.
// (R1 kernel, measured ~70us for K=64.)
// ============================================================================
template<int K>
__global__ void __launch_bounds__(256, 1) gemm_rows(
    const float* __restrict__ X, const float* __restrict__ W, float* __restrict__ OUT)
{
    if (blockIdx.x == 0)
        for (int i = threadIdx.x; i < DB * 32; i += 256) g_prog[i] = 0;

    extern __shared__ float ws[];
    for (int i = threadIdx.x; i < K * DH / 4; i += 256)
        reinterpret_cast<float4*>(ws)[i] = reinterpret_cast<const float4*>(W)[i];
    __syncthreads();

    int row = blockIdx.x * 256 + threadIdx.x;
    const float* xr = X + (size_t)row * K;
    float xv[K];
    #pragma unroll
    for (int i = 0; i < K / 4; i++) {
        float4 v = reinterpret_cast<const float4*>(xr)[i];
        xv[4*i] = v.x; xv[4*i+1] = v.y; xv[4*i+2] = v.z; xv[4*i+3] = v.w;
    }
    const u64* wsu = reinterpret_cast<const u64*>(ws);
    float* outr = OUT + (size_t)row * DH;

    #pragma unroll 1
    for (int cb = 0; cb < 16; cb++) {
        u64 a0 = 0, a1 = 0, a2 = 0, a3 = 0;
        #pragma unroll 16
        for (int k = 0; k < K; k++) {
            u64 xd = dup2(xv[k]);
            const u64* wr = wsu + k * (DH / 2) + cb * 4;
            a0 = ffma2(xd, wr[0], a0);
            a1 = ffma2(xd, wr[1], a1);
            a2 = ffma2(xd, wr[2], a2);
            a3 = ffma2(xd, wr[3], a3);
        }
        float2 r0 = unp2(a0), r1 = unp2(a1), r2 = unp2(a2), r3 = unp2(a3);
        reinterpret_cast<float4*>(outr)[cb*2]     = make_float4(r0.x, r0.y, r1.x, r1.y);
        reinterpret_cast<float4*>(outr)[cb*2 + 1] = make_float4(r2.x, r2.y, r3.x, r3.y);
    }
}

// ---------------- shared memory ------------------------------------------------
struct ScanSM {                    // R1 layout: h duplicated pairs + 4 partials
    float hdup[2][2 * DH];         // 2KB
    float part[4][DH];             // 2KB
};
struct ChaseSM {
    float stage[8 * DH];           // 4KB
    u64   part[4][8][64];          // 16KB (q partials per row/colpair)
};
union PipeSM { ScanSM s; ChaseSM c; };

// ============================================================================
// R1 scan core (measured 540 ns/step), parameterized with optional flag
// wait (consumer) / post (producer). Thread = (colpair c2 = tid&63,
// k-quarter kq = tid>>6). Two barriers per step.
// ============================================================================
__device__ __forceinline__ void scan_core(
    ScanSM& sm,
    const float* __restrict__ umat, const float* __restrict__ wx,
    const float* __restrict__ bg, const float* __restrict__ bu,
    const float* __restrict__ zeta, const float* __restrict__ nu,
    const float* __restrict__ lambd, const float* __restrict__ gamma,
    float* __restrict__ outp, float* __restrict__ hT,
    const int* pwait, int* ppost, int tid)
{
    const int c2 = tid & 63;
    const int kq = tid >> 6;
    const int j0 = 2 * c2;

    u64 uk[32];
    #pragma unroll
    for (int kk = 0; kk < 32; kk++)
        uk[kk] = *reinterpret_cast<const u64*>(umat + (size_t)(kq * 32 + kk) * DH + j0);

    const float sz   = sigm_fast(zeta[0]);
    const float sn   = sigm_fast(nu[0]);
    const float gc   = fminf(fmaxf(gamma[0], 0.f), 1.f);
    const float cadd = (1.f - gc) * lambd[0];

    for (int i = tid; i < 2 * 2 * DH; i += 256) (&sm.hdup[0][0])[i] = 0.f;

    float bgj = 0.f, buj = 0.f, hold = 0.f, wxA = 0.f, wxB = 0.f;
    if (tid < DH) { bgj = bg[tid]; buj = bu[tid]; }
    if (pwait && tid == 0) spin_ge(pwait, 16);
    __syncthreads();
    if (tid < DH) { wxA = wx[tid]; wxB = wx[DH + tid]; }

    const float* pf = &sm.part[0][0];

    #pragma unroll 1
    for (int s = 0; s < DS; s++) {
        if (pwait && (s & 7) == 0 && s) {
            if (tid == 0) {
                int t = s + 16; if (t > DS) t = DS;
                spin_ge(pwait, t);
            }
            __syncthreads();
        }
        const int cur = s & 1;
        // ---- matvec phase (all 8 warps) ----
        const u64* hb = reinterpret_cast<const u64*>(&sm.hdup[cur][kq * 64]);
        u64 a0 = 0, a1 = 0, a2 = 0, a3 = 0;
        #pragma unroll
        for (int t = 0; t < 8; t++) {
            a0 = ffma2(hb[4*t + 0], uk[4*t + 0], a0);
            a1 = ffma2(hb[4*t + 1], uk[4*t + 1], a1);
            a2 = ffma2(hb[4*t + 2], uk[4*t + 2], a2);
            a3 = ffma2(hb[4*t + 3], uk[4*t + 3], a3);
        }
        *reinterpret_cast<u64*>(&sm.part[kq][j0]) =
            fadd2(fadd2(a0, a1), fadd2(a2, a3));
        __syncthreads();

        // ---- gate phase (warps 0-3) ----
        if (tid < DH) {
            float pre = wxA + ((pf[tid] + pf[DH + tid]) +
                               (pf[2*DH + tid] + pf[3*DH + tid]));
            float zg = sigm_fast(pre + bgj);
            float th = tanh_fast(pre + buj);
            float hn = zg * hold + (sz * (1.f - zg) + sn) * th;
            float hc = __fmaf_rn(gc, hn, cadd);
            outp[(size_t)s * DH + tid] = hc;
            hold = hc;
            reinterpret_cast<float2*>(&sm.hdup[cur ^ 1][0])[tid] =
                make_float2(hc, hc);
            wxA = wxB;
            wxB = (s + 2 < DS) ? __ldg(&wx[(size_t)(s + 2) * DH + tid]) : 0.f;
        }
        __syncthreads();
        if (ppost && (s & 7) == 7 && tid == 0) {
            __threadfence();
            st_rel(ppost, s + 1);
        }
    }
    if (tid < DH) hT[tid] = hold;
    if (ppost) {
        __syncthreads();
        if (tid == 0) { __threadfence(); st_rel(ppost, DS + 64); }
    }
}

// ============================================================================
// wx1 chase CTA: wx1[t,:] = out0[t,:] @ w1 in 8-row chunks, trailing p0 by
// >=16 rows (visibility margin). Thread = (colpair c = tid&63, kq = tid>>6).
// ============================================================================
__device__ __forceinline__ void chase_core(
    ChaseSM& sm,
    const float* __restrict__ out0b, const float* __restrict__ w1,
    float* __restrict__ wx1b, const int* p0, int* pwx1, int tid)
{
    const int c = tid & 63;
    const int q = tid >> 6;

    u64 uw[16];
    #pragma unroll
    for (int i = 0; i < 16; i++)
        uw[i] = *reinterpret_cast<const u64*>(w1 + (size_t)(q * 32 + 2 * i) * DH + 2 * c)
              , uw[i] = uw[i];   // keep simple; second pair loaded below
    u64 uw2[16];
    #pragma unroll
    for (int i = 0; i < 16; i++)
        uw2[i] = *reinterpret_cast<const u64*>(w1 + (size_t)(q * 32 + 2 * i + 1) * DH + 2 * c);

    #pragma unroll 1
    for (int n = 0; n < DS / 8; n++) {
        const int t0 = 8 * n;
        if (tid == 0) {
            int tgt = t0 + 16; if (tgt > DS) tgt = DS + 64;   // last chunk: wait full finish
            if (t0 + 16 <= DS) tgt = t0 + 16;
            spin_ge(p0, tgt);
        }
        __syncthreads();
        // stage 8 rows (1024 floats = 256 float4)
        reinterpret_cast<float4*>(sm.stage)[tid] =
            reinterpret_cast<const float4*>(out0b + (size_t)t0 * DH)[tid];
        __syncthreads();

        u64 accs[8];
        #pragma unroll
        for (int r = 0; r < 8; r++) {
            const float2* hr = reinterpret_cast<const float2*>(sm.stage + r * DH + q * 32);
            u64 acc0 = 0, acc1 = 0;
            #pragma unroll
            for (int i = 0; i < 16; i++) {
                float2 v = hr[i];
                acc0 = ffma2(dup2(v.x), uw[i],  acc0);
                acc1 = ffma2(dup2(v.y), uw2[i], acc1);
            }
            accs[r] = fadd2(acc0, acc1);
        }
        #pragma unroll
        for (int r = 0; r < 8; r++) sm.part[q][r][c] = accs[r];
        __syncthreads();
        // combine 4 quarters: 512 outputs / 256 threads = 2 each
        #pragma unroll
        for (int o = 0; o < 2; o++) {
            int idx = tid + o * 256;
            int r = idx >> 6, cc = idx & 63;
            u64 t = fadd2(fadd2(sm.part[0][r][cc], sm.part[1][r][cc]),
                          fadd2(sm.part[2][r][cc], sm.part[3][r][cc]));
            *reinterpret_cast<u64*>(wx1b + (size_t)(t0 + r) * DH + 2 * cc) = t;
        }
        __threadfence();
        __syncthreads();
        if (tid == 0) st_rel(pwx1, t0 + 8);
    }
}

// ============================================================================
__global__ void __launch_bounds__(256, 1) pipe_kernel(
    const float* __restrict__ u0, const float* __restrict__ u1,
    const float* __restrict__ w1,
    const float* __restrict__ bg0, const float* __restrict__ bu0,
    const float* __restrict__ zeta0, const float* __restrict__ nu0,
    const float* __restrict__ lambd0, const float* __restrict__ gamma0,
    const float* __restrict__ bg1, const float* __restrict__ bu1,
    const float* __restrict__ zeta1, const float* __restrict__ nu1,
    const float* __restrict__ lambd1, const float* __restrict__ gamma1,
    float* __restrict__ out1, float* __restrict__ hT0, float* __restrict__ hT1)
{
    __shared__ __align__(16) PipeSM sm;

    const int tid  = threadIdx.x;
    const int role = blockIdx.x >> 6;   // 0=producer, 1=consumer, 2=wx1 chase
    const int b    = blockIdx.x & 63;

    float*       out0b = g_out0 + (size_t)b * DS * DH;
    const float* wx0b  = g_wx0  + (size_t)b * DS * DH;
    float*       wx1b  = g_wx1  + (size_t)b * DS * DH;
    int*         p0    = g_prog + b * 32;
    int*         pwx1  = g_prog + b * 32 + 16;

    if (role == 0) {
        scan_core(sm.s, u0, wx0b, bg0, bu0, zeta0, nu0, lambd0, gamma0,
                  out0b, hT0 + (size_t)b * DH, nullptr, p0, tid);
    } else if (role == 1) {
        scan_core(sm.s, u1, wx1b, bg1, bu1, zeta1, nu1, lambd1, gamma1,
                  out1 + (size_t)b * DS * DH, hT1 + (size_t)b * DH,
                  pwx1, nullptr, tid);
    } else {
        chase_core(sm.c, out0b, w1, wx1b, p0, pwx1, tid);
    }
}

// ============================================================================
extern "C" void kernel_launch(void* const* d_in, const int* in_sizes, int n_in,
                              void* d_out, int out_size)
{
    const float* x      = (const float*)d_in[0];
    const float* w0     = (const float*)d_in[1];
    const float* u0     = (const float*)d_in[2];
    const float* bg0    = (const float*)d_in[3];
    const float* bu0    = (const float*)d_in[4];
    const float* zeta0  = (const float*)d_in[5];
    const float* nu0    = (const float*)d_in[6];
    const float* lambd0 = (const float*)d_in[7];
    const float* gamma0 = (const float*)d_in[8];
    const float* w1     = (const float*)d_in[9];
    const float* u1     = (const float*)d_in[10];
    const float* bg1    = (const float*)d_in[11];
    const float* bu1    = (const float*)d_in[12];
    const float* zeta1  = (const float*)d_in[13];
    const float* nu1    = (const float*)d_in[14];
    const float* lambd1 = (const float*)d_in[15];
    const float* gamma1 = (const float*)d_in[16];
    (void)in_sizes; (void)n_in; (void)out_size;

    float* out = (float*)d_out;                    // out1: [B, S, H]
    float* hT0 = out + (size_t)DB * DS * DH;       // h_n[0]
    float* hT1 = hT0 + (size_t)DB * DH;            // h_n[1]

    void* p;
    cudaGetSymbolAddress(&p, g_wx0);
    float* wx0p = (float*)p;

    static int smem_set = 0;
    if (!smem_set) {
        cudaFuncSetAttribute(gemm_rows<DI>,
                             cudaFuncAttributeMaxDynamicSharedMemorySize, DI * DH * 4);
        smem_set = 1;
    }

    gemm_rows<DI><<<(DB * DS) / 256, 256, DI * DH * 4>>>(x, w0, wx0p);
    pipe_kernel<<<3 * DB, 256>>>(
        u0, u1, w1,
        bg0, bu0, zeta0, nu0, lambd0, gamma0,
        bg1, bu1, zeta1, nu1, lambd1, gamma1,
        out, hT0, hT1);
}